// round 10
// baseline (speedup 1.0000x reference)
#include <cuda_runtime.h>

// LocalCorrRatio, single launch. Shared-weight decomposition + ticket gathers
// (release/acquire, no MEMBAR) + incremental double-atomic eta accumulation.
// Block p: per-sub-region bin partials ({4,5}^3 split at local coord 4),
// 2 shift-0 etas -> g_sum, publish partials, ticket-signal 8 shifted patches;
// 8th contributor gathers that patch's 2 etas inline. Completion counter
// (1000 blocks + 1000 wins = 2000, acq_rel) elects output writer. Self-reset.

#define NPATCH 1000
#define W3 729
#define DIM 90
#define KEXP2 (-1386.4299343f)    // -961 * log2(e)
#define K2N   (2772.8598686f)     // -2 * KEXP2
#define MXS   (3.60637e-4f)       // -1/(2*KEXP2): x = v * MXS

__device__ float g_part[NPATCH * 8 * 4 * 32];   // [p][s][v][bin] v: SwA,SxA,SwB,SxB
__device__ float g_stats[NPATCH * 8 * 4];       // [p][s][{sumT,sumT2,sumP,sumP2}]
__device__ unsigned int g_ready[NPATCH];        // zero-init; winner resets
__device__ unsigned int g_count = 0;
__device__ double g_sum = 0.0;

__constant__ int cBASE[8]  = {0, 64, 144, 224, 324, 404, 504, 604};
__constant__ int cSPLIT[8] = {64, 144, 224, 324, 404, 504, 604, 729};

__device__ __forceinline__ float ex2(float x) {
    float r; asm("ex2.approx.f32 %0, %1;" : "=f"(r) : "f"(x)); return r;
}
__device__ __forceinline__ unsigned int atom_acqrel_add(unsigned int* a, unsigned int v) {
    unsigned int old;
    asm volatile("atom.acq_rel.gpu.global.add.u32 %0, [%1], %2;"
                 : "=r"(old) : "l"(a), "r"(v) : "memory");
    return old;
}

__device__ __forceinline__ void finalize_eta(int dir, int lane, float Sw, float Sx,
                                             float sT, float sT2, float sP, float sP2) {
    float sx  = (dir == 0) ? sT  : sP;
    float sx2 = (dir == 0) ? sT2 : sP2;
    float mean = sx * (1.0f / (float)W3);
    float var  = (sx2 - sx * sx * (1.0f / (float)W3)) * (1.0f / (float)(W3 - 1));
    float mi = Sx / (Sw + 1e-5f);
    float dm = mi - mean;
    float num = Sw * dm * dm;
    float den = Sw;
    #pragma unroll
    for (int o = 16; o; o >>= 1) {
        num += __shfl_xor_sync(0xffffffffu, num, o);
        den += __shfl_xor_sync(0xffffffffu, den, o);
    }
    if (lane == 0) atomicAdd(&g_sum, (double)((num / den) / (var + 1e-5f)));
}

__global__ __launch_bounds__(256, 8) void lcr_kernel(const float* __restrict__ yt,
                                                     const float* __restrict__ yp,
                                                     float* __restrict__ out) {
    const int p = blockIdx.x;
    const int ph = p / 100;
    const int pw = (p / 10) % 10;
    const int pd = p % 10;

    __shared__ float ts[W3];
    __shared__ float ps[W3];
    __shared__ __align__(16) float4 uv[W3];    // {uT, vT, uP, vP}
    __shared__ float part_a[8][4][32];
    __shared__ float part_b[8][4][32];
    __shared__ float stats_sm[8][4];
    __shared__ int s_win[8];
    __shared__ int s_nwins;

    const int tid = threadIdx.x;
    const int warp = tid >> 5;
    const int lane = tid & 31;
    const float cb = (float)lane * (1.0f / 31.0f);
    const float cc = KEXP2 * cb * cb;

    // ---- Load patch into sub-region-major order; precompute u,v ----
    for (int idx = tid; idx < W3; idx += 256) {
        int i = idx / 81;
        int r = idx - i * 81;
        int j = r / 9;
        int k = r - j * 9;
        int g = ((ph * 9 + i) * DIM + (pw * 9 + j)) * DIM + (pd * 9 + k);
        float tv = yt[g];
        float pv = yp[g];
        int sh = (i >= 4), sw_ = (j >= 4), sd_ = (k >= 4);
        int s = (sh << 2) | (sw_ << 1) | sd_;
        int ii = i - (sh ? 4 : 0);
        int jj = j - (sw_ ? 4 : 0);
        int kk = k - (sd_ ? 4 : 0);
        int nw = sw_ ? 5 : 4;
        int nd = sd_ ? 5 : 4;
        int dest = cBASE[s] + (ii * nw + jj) * nd + kk;
        ts[dest] = tv;
        ps[dest] = pv;
        uv[dest] = make_float4(KEXP2 * tv * tv, K2N * tv,
                               KEXP2 * pv * pv, K2N * pv);
    }
    __syncthreads();

    // ---- Stats for sub-region s == warp ----
    {
        int b0 = cBASE[warp];
        int b1 = (warp < 7) ? cBASE[warp + 1] : W3;
        float sT = 0.f, sT2 = 0.f, sP = 0.f, sP2 = 0.f;
        for (int idx = b0 + lane; idx < b1; idx += 32) {
            float tv = ts[idx], pv = ps[idx];
            sT += tv;  sT2 = fmaf(tv, tv, sT2);
            sP += pv;  sP2 = fmaf(pv, pv, sP2);
        }
        #pragma unroll
        for (int o = 16; o; o >>= 1) {
            sT  += __shfl_xor_sync(0xffffffffu, sT,  o);
            sT2 += __shfl_xor_sync(0xffffffffu, sT2, o);
            sP  += __shfl_xor_sync(0xffffffffu, sP,  o);
            sP2 += __shfl_xor_sync(0xffffffffu, sP2, o);
        }
        if (lane == 0) {
            stats_sm[warp][0] = sT;  stats_sm[warp][1] = sT2;
            stats_sm[warp][2] = sP;  stats_sm[warp][3] = sP2;
        }
    }

    // ---- Bin sums: lane = bin; warp range split at one static boundary ----
    // w = ex2(fma(v, cb, u) + cc);  x recovered as v * MXS.
    {
        const int s1b = 92 * warp;
        const int s1e = cSPLIT[warp];
        float SwA = 0.f, SxA = 0.f, SwB = 0.f, SxB = 0.f;
        #pragma unroll 4
        for (int idx = s1b; idx < s1e; idx++) {
            float4 q = uv[idx];
            float wA = ex2(fmaf(q.w, cb, q.z) + cc);   // Y = pred
            float wB = ex2(fmaf(q.y, cb, q.x) + cc);   // Y = true
            SwA += wA;  SxA = fmaf(wA, q.y, SxA);      // x = true  (vT)
            SwB += wB;  SxB = fmaf(wB, q.w, SxB);      // x = pred  (vP)
        }
        part_a[warp][0][lane] = SwA;
        part_a[warp][1][lane] = SxA * MXS;
        part_a[warp][2][lane] = SwB;
        part_a[warp][3][lane] = SxB * MXS;

        if (warp < 7) {
            const int s2b = s1e;
            const int s2e = 92 * warp + 92;
            SwA = 0.f; SxA = 0.f; SwB = 0.f; SxB = 0.f;
            #pragma unroll 4
            for (int idx = s2b; idx < s2e; idx++) {
                float4 q = uv[idx];
                float wA = ex2(fmaf(q.w, cb, q.z) + cc);
                float wB = ex2(fmaf(q.y, cb, q.x) + cc);
                SwA += wA;  SxA = fmaf(wA, q.y, SxA);
                SwB += wB;  SxB = fmaf(wB, q.w, SxB);
            }
            part_b[warp + 1][0][lane] = SwA;
            part_b[warp + 1][1][lane] = SxA * MXS;
            part_b[warp + 1][2][lane] = SwB;
            part_b[warp + 1][3][lane] = SxB * MXS;
        }
    }
    __syncthreads();

    // ---- Combine per sub-region, publish to gmem ----
    {
        const int s = warp;
        float v0 = part_a[s][0][lane];
        float v1 = part_a[s][1][lane];
        float v2 = part_a[s][2][lane];
        float v3 = part_a[s][3][lane];
        if (s >= 1) {
            v0 += part_b[s][0][lane];
            v1 += part_b[s][1][lane];
            v2 += part_b[s][2][lane];
            v3 += part_b[s][3][lane];
        }
        part_a[s][0][lane] = v0;
        part_a[s][1][lane] = v1;
        part_a[s][2][lane] = v2;
        part_a[s][3][lane] = v3;
        int gb = ((p * 8 + s) * 4) * 32 + lane;
        g_part[gb]      = v0;
        g_part[gb + 32] = v1;
        g_part[gb + 64] = v2;
        g_part[gb + 96] = v3;
        if (lane < 4) g_stats[(p * 8 + s) * 4 + lane] = stats_sm[s][lane];
    }
    __syncthreads();   // block's partial stores happen-before the tickets below

    // ---- Ticket-signal the 8 shifted patches this block feeds (acq_rel:
    //      release our stores; 8th arriver acquires the other 7 blocks'). ----
    if (tid < 8) {
        if (tid == 0) s_nwins = 0;
        int cc2 = 7 - tid;
        int dh = (cc2 >> 2) & 1, dw = (cc2 >> 1) & 1, dd = cc2 & 1;
        int pa = ph - dh; if (pa < 0) pa += 10;
        int pb = pw - dw; if (pb < 0) pb += 10;
        int pc = pd - dd; if (pc < 0) pc += 10;
        int pt = (pa * 10 + pb) * 10 + pc;
        unsigned int old = atom_acqrel_add(&g_ready[pt], 1u);
        s_win[tid] = (old == 7u) ? pt : -1;
        if (old == 7u) atomicAdd(&s_nwins, 1);
    }

    // ---- Shift-0 etas (variants 0 and 1) -> g_sum ----
    if (warp < 2) {
        const int v0 = warp * 2;
        float Sw = 0.f, Sx = 0.f;
        #pragma unroll
        for (int s = 0; s < 8; s++) { Sw += part_a[s][v0][lane]; Sx += part_a[s][v0 + 1][lane]; }
        float sT = 0.f, sT2 = 0.f, sP = 0.f, sP2 = 0.f;
        #pragma unroll
        for (int s = 0; s < 8; s++) {
            sT += stats_sm[s][0]; sT2 += stats_sm[s][1];
            sP += stats_sm[s][2]; sP2 += stats_sm[s][3];
        }
        finalize_eta(warp, lane, Sw, Sx, sT, sT2, sP, sP2);
    }
    __syncthreads();

    // ---- Gather etas for shifted patches this block won (L2 loads) ----
    if (s_nwins > 0) {
        #pragma unroll 1
        for (int i = 0; i < 8; i++) {
            int pt = s_win[i];
            if (pt < 0) continue;
            if (warp < 2) {
                int a = pt / 100, b = (pt / 10) % 10, c = pt % 10;
                float Sw = 0.f, Sx = 0.f;
                float sT = 0.f, sT2 = 0.f, sP = 0.f, sP2 = 0.f;
                #pragma unroll
                for (int cc2 = 0; cc2 < 8; cc2++) {
                    int dh = (cc2 >> 2) & 1, dw = (cc2 >> 1) & 1, dd = cc2 & 1;
                    int qa = a + dh; if (qa >= 10) qa -= 10;
                    int qb = b + dw; if (qb >= 10) qb -= 10;
                    int qc = c + dd; if (qc >= 10) qc -= 10;
                    int q = (qa * 10 + qb) * 10 + qc;
                    int s = 7 - cc2;
                    int gb = ((q * 8 + s) * 4 + warp * 2) * 32;
                    Sw += __ldcg(&g_part[gb + lane]);
                    Sx += __ldcg(&g_part[gb + 32 + lane]);
                    int sb = (q * 8 + s) * 4;
                    sT  += __ldcg(&g_stats[sb + 0]);
                    sT2 += __ldcg(&g_stats[sb + 1]);
                    sP  += __ldcg(&g_stats[sb + 2]);
                    sP2 += __ldcg(&g_stats[sb + 3]);
                }
                finalize_eta(warp, lane, Sw, Sx, sT, sT2, sP, sP2);
            }
            if (tid == 0) g_ready[pt] = 0;   // all 8 arrivals already in; reset
        }
    }

    // ---- Completion counting (2000 units); last unit writes output ----
    __syncthreads();
    if (tid == 0) {
        unsigned int add = 1u + (unsigned)s_nwins;
        unsigned int old = atom_acqrel_add(&g_count, add);
        if (old + add == 2000u) {
            double s = *((volatile double*)&g_sum);
            out[0] = (float)(-s / 12000.0);
            g_sum = 0.0;
            g_count = 0;
        }
    }
}

extern "C" void kernel_launch(void* const* d_in, const int* in_sizes, int n_in,
                              void* d_out, int out_size) {
    const float* y_true = (const float*)d_in[0];
    const float* y_pred = (const float*)d_in[1];
    float* out = (float*)d_out;
    lcr_kernel<<<NPATCH, 256>>>(y_true, y_pred, out);
}

// round 11
// speedup vs baseline: 1.2564x; 1.2564x over previous
#include <cuda_runtime.h>

// LocalCorrRatio via shared-weight decomposition (two kernels, R5 tail).
// Kernel 1 (optimized): block = shift-0 patch. Voxels stored as float4
// {u_t, v_t, u_p, v_p} with u=K*y^2, v=-2K*y so the Parzen weight is
// w = ex2(fma(v, cb, u) + K*cb^2), and x / stats are recovered linearly
// (y = v*MXS, y^2 = u/K). Per-sub-region bin partials ({4,5}^3 split at
// local coord 4), 2 shift-0 etas, publish partials + stats.
// Kernel 2 (R5 verbatim): block = shifted patch (64 thr), gathers 8
// contributors' partials, 2 shifted etas; last block reduces all 4000.

#define NPATCH 1000
#define W3 729
#define DIM 90
#define KEXP2 (-1386.4299343f)    // K = -961 * log2(e)
#define K2N   (2772.8598686f)     // -2K
#define MXS   (1.0f / 2772.8598686f)   // -1/(2K): y = v * MXS
#define KINV  (-1.0f / 1386.4299343f)  // 1/K: y^2 = u * KINV

__device__ float g_part[NPATCH * 8 * 4 * 32];   // [p][s][v][bin] v: SwA,SxA,SwB,SxB
__device__ float g_stats[NPATCH * 8 * 4];       // [p][s][{sumT,sumT2,sumP,sumP2}]
__device__ float g_eta[4 * NPATCH];
__device__ unsigned int g_count = 0;

__constant__ int cBASE[8]  = {0, 64, 144, 224, 324, 404, 504, 604};
__constant__ int cSPLIT[8] = {64, 144, 224, 324, 404, 504, 604, 729};

__device__ __forceinline__ float ex2(float x) {
    float r; asm("ex2.approx.f32 %0, %1;" : "=f"(r) : "f"(x)); return r;
}

__device__ __forceinline__ void finalize_eta(int dir, int lane, float Sw, float Sx,
                                             float sT, float sT2, float sP, float sP2,
                                             float* dst) {
    float sx  = (dir == 0) ? sT  : sP;
    float sx2 = (dir == 0) ? sT2 : sP2;
    float mean = sx * (1.0f / (float)W3);
    float var  = (sx2 - sx * sx * (1.0f / (float)W3)) * (1.0f / (float)(W3 - 1));
    float mi = Sx / (Sw + 1e-5f);
    float dm = mi - mean;
    float num = Sw * dm * dm;
    float den = Sw;
    #pragma unroll
    for (int o = 16; o; o >>= 1) {
        num += __shfl_xor_sync(0xffffffffu, num, o);
        den += __shfl_xor_sync(0xffffffffu, den, o);
    }
    if (lane == 0) *dst = (num / den) / (var + 1e-5f);
}

__global__ __launch_bounds__(256, 8) void lcr_part_kernel(const float* __restrict__ yt,
                                                          const float* __restrict__ yp) {
    const int p = blockIdx.x;
    const int ph = p / 100;
    const int pw = (p / 10) % 10;
    const int pd = p % 10;

    __shared__ __align__(16) float4 uv[W3];    // {uT, vT, uP, vP}
    __shared__ float part_a[8][4][32];
    __shared__ float part_b[8][4][32];
    __shared__ float stats_sm[8][4];

    const int tid = threadIdx.x;
    const int warp = tid >> 5;
    const int lane = tid & 31;
    const float cb = (float)lane * (1.0f / 31.0f);
    const float cc = KEXP2 * cb * cb;

    // ---- Load patch into sub-region-major order; precompute u,v ----
    for (int idx = tid; idx < W3; idx += 256) {
        int i = idx / 81;
        int r = idx - i * 81;
        int j = r / 9;
        int k = r - j * 9;
        int g = ((ph * 9 + i) * DIM + (pw * 9 + j)) * DIM + (pd * 9 + k);
        float tv = yt[g];
        float pv = yp[g];
        int sh = (i >= 4), sw_ = (j >= 4), sd_ = (k >= 4);
        int s = (sh << 2) | (sw_ << 1) | sd_;
        int ii = i - (sh ? 4 : 0);
        int jj = j - (sw_ ? 4 : 0);
        int kk = k - (sd_ ? 4 : 0);
        int nw = sw_ ? 5 : 4;
        int nd = sd_ ? 5 : 4;
        int dest = cBASE[s] + (ii * nw + jj) * nd + kk;
        uv[dest] = make_float4(KEXP2 * tv * tv, K2N * tv,
                               KEXP2 * pv * pv, K2N * pv);
    }
    __syncthreads();

    // ---- Stats for sub-region s == warp (linear recovery from u,v) ----
    {
        int b0 = cBASE[warp];
        int b1 = (warp < 7) ? cBASE[warp + 1] : W3;
        float suT = 0.f, svT = 0.f, suP = 0.f, svP = 0.f;
        for (int idx = b0 + lane; idx < b1; idx += 32) {
            float4 q = uv[idx];
            suT += q.x;  svT += q.y;
            suP += q.z;  svP += q.w;
        }
        #pragma unroll
        for (int o = 16; o; o >>= 1) {
            suT += __shfl_xor_sync(0xffffffffu, suT, o);
            svT += __shfl_xor_sync(0xffffffffu, svT, o);
            suP += __shfl_xor_sync(0xffffffffu, suP, o);
            svP += __shfl_xor_sync(0xffffffffu, svP, o);
        }
        if (lane == 0) {
            stats_sm[warp][0] = svT * MXS;    // sum t
            stats_sm[warp][1] = suT * KINV;   // sum t^2
            stats_sm[warp][2] = svP * MXS;    // sum p
            stats_sm[warp][3] = suP * KINV;   // sum p^2
        }
    }

    // ---- Bin sums: lane = bin; warp range split at one static boundary ----
    // w = ex2(fma(v, cb, u) + cc);  x recovered as v * MXS at segment end.
    {
        const int s1b = 92 * warp;
        const int s1e = cSPLIT[warp];
        float SwA = 0.f, SxA = 0.f, SwB = 0.f, SxB = 0.f;
        #pragma unroll 4
        for (int idx = s1b; idx < s1e; idx++) {
            float4 q = uv[idx];
            float wA = ex2(fmaf(q.w, cb, q.z) + cc);   // Y = pred
            float wB = ex2(fmaf(q.y, cb, q.x) + cc);   // Y = true
            SwA += wA;  SxA = fmaf(wA, q.y, SxA);      // x = true  (vT)
            SwB += wB;  SxB = fmaf(wB, q.w, SxB);      // x = pred  (vP)
        }
        part_a[warp][0][lane] = SwA;
        part_a[warp][1][lane] = SxA * MXS;
        part_a[warp][2][lane] = SwB;
        part_a[warp][3][lane] = SxB * MXS;

        if (warp < 7) {
            const int s2b = s1e;
            const int s2e = 92 * warp + 92;
            SwA = 0.f; SxA = 0.f; SwB = 0.f; SxB = 0.f;
            #pragma unroll 4
            for (int idx = s2b; idx < s2e; idx++) {
                float4 q = uv[idx];
                float wA = ex2(fmaf(q.w, cb, q.z) + cc);
                float wB = ex2(fmaf(q.y, cb, q.x) + cc);
                SwA += wA;  SxA = fmaf(wA, q.y, SxA);
                SwB += wB;  SxB = fmaf(wB, q.w, SxB);
            }
            part_b[warp + 1][0][lane] = SwA;
            part_b[warp + 1][1][lane] = SxA * MXS;
            part_b[warp + 1][2][lane] = SwB;
            part_b[warp + 1][3][lane] = SxB * MXS;
        }
    }
    __syncthreads();

    // ---- Combine per sub-region, publish to gmem ----
    {
        const int s = warp;
        float v0 = part_a[s][0][lane];
        float v1 = part_a[s][1][lane];
        float v2 = part_a[s][2][lane];
        float v3 = part_a[s][3][lane];
        if (s >= 1) {
            v0 += part_b[s][0][lane];
            v1 += part_b[s][1][lane];
            v2 += part_b[s][2][lane];
            v3 += part_b[s][3][lane];
        }
        part_a[s][0][lane] = v0;
        part_a[s][1][lane] = v1;
        part_a[s][2][lane] = v2;
        part_a[s][3][lane] = v3;
        int gb = ((p * 8 + s) * 4) * 32 + lane;
        g_part[gb]      = v0;
        g_part[gb + 32] = v1;
        g_part[gb + 64] = v2;
        g_part[gb + 96] = v3;
        if (lane < 4) g_stats[(p * 8 + s) * 4 + lane] = stats_sm[s][lane];
    }
    __syncthreads();

    // ---- Shift-0 etas (variants 0 and 1) ----
    if (warp < 2) {
        const int v0 = warp * 2;
        float Sw = 0.f, Sx = 0.f;
        #pragma unroll
        for (int s = 0; s < 8; s++) { Sw += part_a[s][v0][lane]; Sx += part_a[s][v0 + 1][lane]; }
        float sT = 0.f, sT2 = 0.f, sP = 0.f, sP2 = 0.f;
        #pragma unroll
        for (int s = 0; s < 8; s++) {
            sT += stats_sm[s][0]; sT2 += stats_sm[s][1];
            sP += stats_sm[s][2]; sP2 += stats_sm[s][3];
        }
        finalize_eta(warp, lane, Sw, Sx, sT, sT2, sP, sP2,
                     &g_eta[warp * NPATCH + p]);
    }
}

__global__ __launch_bounds__(64) void lcr_final_kernel(float* __restrict__ out) {
    const int p = blockIdx.x;
    const int a = p / 100;
    const int b = (p / 10) % 10;
    const int c = p % 10;
    const int tid = threadIdx.x;
    const int warp = tid >> 5;    // 0: dir A (variant 2), 1: dir B (variant 3)
    const int lane = tid & 31;

    __shared__ unsigned int s_islast;

    float Sw = 0.f, Sx = 0.f;
    float sT = 0.f, sT2 = 0.f, sP = 0.f, sP2 = 0.f;
    #pragma unroll
    for (int cc = 0; cc < 8; cc++) {
        int dh = (cc >> 2) & 1, dw = (cc >> 1) & 1, dd = cc & 1;
        int qa = a + dh; if (qa >= 10) qa -= 10;
        int qb = b + dw; if (qb >= 10) qb -= 10;
        int qc = c + dd; if (qc >= 10) qc -= 10;
        int q = (qa * 10 + qb) * 10 + qc;
        int s = 7 - cc;                 // delta=0 -> hi half, delta=1 -> lo half
        int gb = ((q * 8 + s) * 4 + warp * 2) * 32;
        Sw += g_part[gb + lane];
        Sx += g_part[gb + 32 + lane];
        int sb = (q * 8 + s) * 4;
        sT  += g_stats[sb + 0];
        sT2 += g_stats[sb + 1];
        sP  += g_stats[sb + 2];
        sP2 += g_stats[sb + 3];
    }
    finalize_eta(warp, lane, Sw, Sx, sT, sT2, sP, sP2,
                 &g_eta[(2 + warp) * NPATCH + p]);

    __threadfence();
    __syncthreads();
    if (tid == 0) {
        unsigned int old = atomicAdd(&g_count, 1u);
        s_islast = (old == NPATCH - 1) ? 1u : 0u;
    }
    __syncthreads();
    if (s_islast) {
        __threadfence();
        __shared__ double sh[64];
        double s = 0.0;
        for (int i = tid; i < 4 * NPATCH; i += 64) s += (double)g_eta[i];
        sh[tid] = s;
        __syncthreads();
        #pragma unroll
        for (int o = 32; o; o >>= 1) {
            if (tid < o) sh[tid] += sh[tid + o];
            __syncthreads();
        }
        if (tid == 0) {
            out[0] = (float)(-sh[0] / 12000.0);
            g_count = 0;
        }
    }
}

extern "C" void kernel_launch(void* const* d_in, const int* in_sizes, int n_in,
                              void* d_out, int out_size) {
    const float* y_true = (const float*)d_in[0];
    const float* y_pred = (const float*)d_in[1];
    float* out = (float*)d_out;
    lcr_part_kernel<<<NPATCH, 256>>>(y_true, y_pred);
    lcr_final_kernel<<<NPATCH, 64>>>(out);
}

// round 12
// speedup vs baseline: 1.4989x; 1.1930x over previous
#include <cuda_runtime.h>

// LocalCorrRatio via shared-weight decomposition (two kernels, fence-free tail).
// Kernel 1: block = shift-0 patch. Voxels as float4 {uT,vT,uP,vP}, u=K*y^2,
// v=-2K*y so w = ex2(fma(v,cb,u) + K*cb^2); stats recovered linearly.
// Per-sub-region bin partials ({4,5}^3 split at local coord 4); the 2 shift-0
// etas are atomicAdd'ed (double) into g_sum; publish partials + stats.
// Kernel 2: block = shifted patch (64 thr); gathers 8 contributors' partials,
// adds its 2 etas to g_sum; acq_rel completion counter; last arriver writes out.
// No MEMBAR anywhere. All globals self-reset for graph replay.

#define NPATCH 1000
#define W3 729
#define DIM 90
#define KEXP2 (-1386.4299343f)    // K = -961 * log2(e)
#define K2N   (2772.8598686f)     // -2K
#define MXS   (1.0f / 2772.8598686f)   // -1/(2K): y = v * MXS
#define KINV  (-1.0f / 1386.4299343f)  // 1/K: y^2 = u * KINV

__device__ float g_part[NPATCH * 8 * 4 * 32];   // [p][s][v][bin] v: SwA,SxA,SwB,SxB
__device__ float g_stats[NPATCH * 8 * 4];       // [p][s][{sumT,sumT2,sumP,sumP2}]
__device__ unsigned int g_count = 0;
__device__ double g_sum = 0.0;

__constant__ int cBASE[8]  = {0, 64, 144, 224, 324, 404, 504, 604};
__constant__ int cSPLIT[8] = {64, 144, 224, 324, 404, 504, 604, 729};

__device__ __forceinline__ float ex2(float x) {
    float r; asm("ex2.approx.f32 %0, %1;" : "=f"(r) : "f"(x)); return r;
}
__device__ __forceinline__ unsigned int atom_acqrel_add(unsigned int* a, unsigned int v) {
    unsigned int old;
    asm volatile("atom.acq_rel.gpu.global.add.u32 %0, [%1], %2;"
                 : "=r"(old) : "l"(a), "r"(v) : "memory");
    return old;
}

// Computes eta and atomicAdds it (as double) into g_sum.
__device__ __forceinline__ void finalize_eta(int dir, int lane, float Sw, float Sx,
                                             float sT, float sT2, float sP, float sP2) {
    float sx  = (dir == 0) ? sT  : sP;
    float sx2 = (dir == 0) ? sT2 : sP2;
    float mean = sx * (1.0f / (float)W3);
    float var  = (sx2 - sx * sx * (1.0f / (float)W3)) * (1.0f / (float)(W3 - 1));
    float mi = Sx / (Sw + 1e-5f);
    float dm = mi - mean;
    float num = Sw * dm * dm;
    float den = Sw;
    #pragma unroll
    for (int o = 16; o; o >>= 1) {
        num += __shfl_xor_sync(0xffffffffu, num, o);
        den += __shfl_xor_sync(0xffffffffu, den, o);
    }
    if (lane == 0) atomicAdd(&g_sum, (double)((num / den) / (var + 1e-5f)));
}

__global__ __launch_bounds__(256, 8) void lcr_part_kernel(const float* __restrict__ yt,
                                                          const float* __restrict__ yp) {
    const int p = blockIdx.x;
    const int ph = p / 100;
    const int pw = (p / 10) % 10;
    const int pd = p % 10;

    __shared__ __align__(16) float4 uv[W3];    // {uT, vT, uP, vP}
    __shared__ float part_a[8][4][32];
    __shared__ float part_b[8][4][32];
    __shared__ float stats_sm[8][4];

    const int tid = threadIdx.x;
    const int warp = tid >> 5;
    const int lane = tid & 31;
    const float cb = (float)lane * (1.0f / 31.0f);
    const float cc = KEXP2 * cb * cb;

    // ---- Load patch into sub-region-major order; precompute u,v ----
    for (int idx = tid; idx < W3; idx += 256) {
        int i = idx / 81;
        int r = idx - i * 81;
        int j = r / 9;
        int k = r - j * 9;
        int g = ((ph * 9 + i) * DIM + (pw * 9 + j)) * DIM + (pd * 9 + k);
        float tv = yt[g];
        float pv = yp[g];
        int sh = (i >= 4), sw_ = (j >= 4), sd_ = (k >= 4);
        int s = (sh << 2) | (sw_ << 1) | sd_;
        int ii = i - (sh ? 4 : 0);
        int jj = j - (sw_ ? 4 : 0);
        int kk = k - (sd_ ? 4 : 0);
        int nw = sw_ ? 5 : 4;
        int nd = sd_ ? 5 : 4;
        int dest = cBASE[s] + (ii * nw + jj) * nd + kk;
        uv[dest] = make_float4(KEXP2 * tv * tv, K2N * tv,
                               KEXP2 * pv * pv, K2N * pv);
    }
    __syncthreads();

    // ---- Stats for sub-region s == warp (linear recovery from u,v) ----
    {
        int b0 = cBASE[warp];
        int b1 = (warp < 7) ? cBASE[warp + 1] : W3;
        float suT = 0.f, svT = 0.f, suP = 0.f, svP = 0.f;
        for (int idx = b0 + lane; idx < b1; idx += 32) {
            float4 q = uv[idx];
            suT += q.x;  svT += q.y;
            suP += q.z;  svP += q.w;
        }
        #pragma unroll
        for (int o = 16; o; o >>= 1) {
            suT += __shfl_xor_sync(0xffffffffu, suT, o);
            svT += __shfl_xor_sync(0xffffffffu, svT, o);
            suP += __shfl_xor_sync(0xffffffffu, suP, o);
            svP += __shfl_xor_sync(0xffffffffu, svP, o);
        }
        if (lane == 0) {
            stats_sm[warp][0] = svT * MXS;    // sum t
            stats_sm[warp][1] = suT * KINV;   // sum t^2
            stats_sm[warp][2] = svP * MXS;    // sum p
            stats_sm[warp][3] = suP * KINV;   // sum p^2
        }
    }

    // ---- Bin sums: lane = bin; warp range split at one static boundary ----
    {
        const int s1b = 92 * warp;
        const int s1e = cSPLIT[warp];
        float SwA = 0.f, SxA = 0.f, SwB = 0.f, SxB = 0.f;
        #pragma unroll 4
        for (int idx = s1b; idx < s1e; idx++) {
            float4 q = uv[idx];
            float wA = ex2(fmaf(q.w, cb, q.z) + cc);   // Y = pred
            float wB = ex2(fmaf(q.y, cb, q.x) + cc);   // Y = true
            SwA += wA;  SxA = fmaf(wA, q.y, SxA);      // x = true  (vT)
            SwB += wB;  SxB = fmaf(wB, q.w, SxB);      // x = pred  (vP)
        }
        part_a[warp][0][lane] = SwA;
        part_a[warp][1][lane] = SxA * MXS;
        part_a[warp][2][lane] = SwB;
        part_a[warp][3][lane] = SxB * MXS;

        if (warp < 7) {
            const int s2b = s1e;
            const int s2e = 92 * warp + 92;
            SwA = 0.f; SxA = 0.f; SwB = 0.f; SxB = 0.f;
            #pragma unroll 4
            for (int idx = s2b; idx < s2e; idx++) {
                float4 q = uv[idx];
                float wA = ex2(fmaf(q.w, cb, q.z) + cc);
                float wB = ex2(fmaf(q.y, cb, q.x) + cc);
                SwA += wA;  SxA = fmaf(wA, q.y, SxA);
                SwB += wB;  SxB = fmaf(wB, q.w, SxB);
            }
            part_b[warp + 1][0][lane] = SwA;
            part_b[warp + 1][1][lane] = SxA * MXS;
            part_b[warp + 1][2][lane] = SwB;
            part_b[warp + 1][3][lane] = SxB * MXS;
        }
    }
    __syncthreads();

    // ---- Combine per sub-region, publish to gmem ----
    {
        const int s = warp;
        float v0 = part_a[s][0][lane];
        float v1 = part_a[s][1][lane];
        float v2 = part_a[s][2][lane];
        float v3 = part_a[s][3][lane];
        if (s >= 1) {
            v0 += part_b[s][0][lane];
            v1 += part_b[s][1][lane];
            v2 += part_b[s][2][lane];
            v3 += part_b[s][3][lane];
        }
        part_a[s][0][lane] = v0;
        part_a[s][1][lane] = v1;
        part_a[s][2][lane] = v2;
        part_a[s][3][lane] = v3;
        int gb = ((p * 8 + s) * 4) * 32 + lane;
        g_part[gb]      = v0;
        g_part[gb + 32] = v1;
        g_part[gb + 64] = v2;
        g_part[gb + 96] = v3;
        if (lane < 4) g_stats[(p * 8 + s) * 4 + lane] = stats_sm[s][lane];
    }
    __syncthreads();

    // ---- Shift-0 etas (variants 0 and 1) -> g_sum ----
    if (warp < 2) {
        const int v0 = warp * 2;
        float Sw = 0.f, Sx = 0.f;
        #pragma unroll
        for (int s = 0; s < 8; s++) { Sw += part_a[s][v0][lane]; Sx += part_a[s][v0 + 1][lane]; }
        float sT = 0.f, sT2 = 0.f, sP = 0.f, sP2 = 0.f;
        #pragma unroll
        for (int s = 0; s < 8; s++) {
            sT += stats_sm[s][0]; sT2 += stats_sm[s][1];
            sP += stats_sm[s][2]; sP2 += stats_sm[s][3];
        }
        finalize_eta(warp, lane, Sw, Sx, sT, sT2, sP, sP2);
    }
}

__global__ __launch_bounds__(64) void lcr_final_kernel(float* __restrict__ out) {
    const int p = blockIdx.x;
    const int a = p / 100;
    const int b = (p / 10) % 10;
    const int c = p % 10;
    const int tid = threadIdx.x;
    const int warp = tid >> 5;    // 0: dir A (variant 2), 1: dir B (variant 3)
    const int lane = tid & 31;

    // g_part/g_stats from kernel 1: visible via kernel boundary (L1D flushed
    // per launch on sm_103a) — no fence needed.
    float Sw = 0.f, Sx = 0.f;
    float sT = 0.f, sT2 = 0.f, sP = 0.f, sP2 = 0.f;
    #pragma unroll
    for (int cc = 0; cc < 8; cc++) {
        int dh = (cc >> 2) & 1, dw = (cc >> 1) & 1, dd = cc & 1;
        int qa = a + dh; if (qa >= 10) qa -= 10;
        int qb = b + dw; if (qb >= 10) qb -= 10;
        int qc = c + dd; if (qc >= 10) qc -= 10;
        int q = (qa * 10 + qb) * 10 + qc;
        int s = 7 - cc;                 // delta=0 -> hi half, delta=1 -> lo half
        int gb = ((q * 8 + s) * 4 + warp * 2) * 32;
        Sw += g_part[gb + lane];
        Sx += g_part[gb + 32 + lane];
        int sb = (q * 8 + s) * 4;
        sT  += g_stats[sb + 0];
        sT2 += g_stats[sb + 1];
        sP  += g_stats[sb + 2];
        sP2 += g_stats[sb + 3];
    }
    finalize_eta(warp, lane, Sw, Sx, sT, sT2, sP, sP2);

    // ---- Completion: this block's g_sum adds precede its counter add
    //      (acq_rel release); the last arriver's same atomic acquires all. ----
    __syncthreads();
    if (tid == 0) {
        unsigned int old = atom_acqrel_add(&g_count, 1u);
        if (old == NPATCH - 1u) {
            double s = *((volatile double*)&g_sum);
            out[0] = (float)(-s / 12000.0);
            g_sum = 0.0;      // reset for next graph replay
            g_count = 0;
        }
    }
}

extern "C" void kernel_launch(void* const* d_in, const int* in_sizes, int n_in,
                              void* d_out, int out_size) {
    const float* y_true = (const float*)d_in[0];
    const float* y_pred = (const float*)d_in[1];
    float* out = (float*)d_out;
    lcr_part_kernel<<<NPATCH, 256>>>(y_true, y_pred);
    lcr_final_kernel<<<NPATCH, 64>>>(out);
}